// round 8
// baseline (speedup 1.0000x reference)
#include <cuda_runtime.h>
#include <math.h>

#define C_CLASSES 21
#define CC 441            // C*C
#define TILE_ROWS 256
#define TILE_ELEMS (TILE_ROWS * C_CLASSES)   // 5376
#define EPS 1e-10f

// ---------------------------------------------------------------------------
// alpha_cumprod collapses analytically: beta_i = 1 - ac[i+1]/ac[i] is clipped
// ONLY at i=199 (beta_199 ~ 1-5e-9 > 0.999; beta_198 ~ 0.994 < 0.999; beta>0
// always since cos^2 is decreasing on [0, pi/2]). ac[0] = 1.0f exactly in f32.
//   acum[t]   = ac[t+1]               for t <= 198
//   acum[199] = ac[199] * (1 - 0.999f)
// One cosf per block; verified rel_err ~1.4e-7 vs jnp reference.
// ---------------------------------------------------------------------------
__device__ __forceinline__ float alpha_of(int tb) {
    int idx = tb + 1;
    if (idx > 199) idx = 199;
    const float inv    = 1.0f / (1.0f + 1e-4f);
    const float halfpi = 1.57079632679489662f;
    float s = (float)idx * (1.0f / 200.0f);
    float c = cosf((s + 1e-4f) * inv * halfpi);
    float a = c * c;
    if (tb >= 199) a *= (1.0f - 0.999f);
    return a;
}

// ---------------------------------------------------------------------------
// Fused kernel, 1D grid, GLOBALLY ORDERED roles:
//   bid in [0, B*QX)            : q_t fill  (launches/executes FIRST)
//   bid in [B*QX, B*QX + B*LX)  : logits    (tail waves — minimal SM sharing)
//
// Round-6/7 finding: the qt store stream saturates the per-SM L1tex path;
// interleaved logits blocks steal it. Disjoint launch phases inside ONE
// kernel keep the serial behavior while removing the inter-launch gap.
//
// qt role: 441 threads, one per float4-residue of the CC=441 period. Grid
// stride between iterations is a multiple of 441 floats so each thread's
// float4 payload is loop-invariant: compute once, ITERS streaming STG.128.
// Outputs are never re-read -> st.global.cs (evict-first) to cut L2 churn.
//
// logits role: 256-row smem tile, fully coalesced load/store, conflict-free
// smem row sums (21 and 32 coprime). All 441 threads with bounds guards.
// ---------------------------------------------------------------------------
template <int ITERS>
__global__ __launch_bounds__(441) void fused_kernel(
    const float* __restrict__ x, const int* __restrict__ t,
    float* __restrict__ logits, float4* __restrict__ qt,
    int S, int QX, int LX, int n_qt_blocks,
    int f4_per_batch, int stride_f4) {

    __shared__ float tile[TILE_ELEMS];
    __shared__ float rs[TILE_ROWS];

    const int bid = blockIdx.x;
    const int tid = threadIdx.x;

    if (bid < n_qt_blocks) {
        // ---- q_t fill (hot path: 462 MB of streaming stores) ----
        const int b  = bid / QX;
        const int xq = bid - b * QX;

        const float alpha = alpha_of(__ldg(&t[b]));
        const float ov = (1.0f - alpha) * (float)(1.0 / 21.0);
        const float dv = alpha + ov;

        int p0 = 4 * tid;                    // (4*tid) mod 441
        if (p0 >= CC) p0 -= CC;
        if (p0 >= CC) p0 -= CC;
        if (p0 >= CC) p0 -= CC;
        float v[4];
        #pragma unroll
        for (int k = 0; k < 4; ++k) {
            int p = p0 + k;
            if (p >= CC) p -= CC;
            v[k] = (p % 22 == 0) ? dv : ov;  // diag positions: p = 22*c
        }
        const float4 val = make_float4(v[0], v[1], v[2], v[3]);

        float4* o = qt + (size_t)b * f4_per_batch
                       + (size_t)xq * CC + tid;
        #pragma unroll
        for (int it = 0; it < ITERS; ++it)
            __stcs(&o[(size_t)it * stride_f4], val);
    } else {
        // ---- logits tile (tail waves) ----
        const int idx      = bid - n_qt_blocks;
        const int b        = idx / LX;
        const int tile_idx = idx - b * LX;

        const float alpha = alpha_of(__ldg(&t[b]));
        const float ov = (1.0f - alpha) * (float)(1.0 / 21.0);
        const float dv = alpha + ov;
        const float Lo  = logf(ov + EPS);
        const float dLd = logf(dv + EPS) - Lo;

        const size_t base = ((size_t)b * S + (size_t)tile_idx * TILE_ROWS)
                            * C_CLASSES;

        const float* xin = x + base;
        #pragma unroll
        for (int i = tid; i < TILE_ELEMS; i += 441)
            tile[i] = __ldcs(&xin[i]);
        __syncthreads();

        if (tid < TILE_ROWS) {
            float s = 0.0f;
            const int r0 = tid * C_CLASSES;
            #pragma unroll
            for (int j = 0; j < C_CLASSES; ++j) s += tile[r0 + j];
            rs[tid] = s;
        }
        __syncthreads();

        float* o = logits + base;
        #pragma unroll
        for (int i = tid; i < TILE_ELEMS; i += 441) {
            int row = (int)(((unsigned)i * 6242u) >> 17);  // i/21, i < 5376
            __stcs(&o[i], fmaf(dLd, tile[i], Lo * rs[row]));
        }
    }
}

// ---------------------------------------------------------------------------
// Generic scalar fallbacks for unexpected shapes.
// ---------------------------------------------------------------------------
__global__ void logits_generic_kernel(const float* __restrict__ x,
                                      const int* __restrict__ t,
                                      float* __restrict__ out,
                                      long long rows, int S) {
    long long stride = (long long)gridDim.x * blockDim.x;
    for (long long row = (long long)blockIdx.x * blockDim.x + threadIdx.x;
         row < rows; row += stride) {
        int b = (int)(row / S);
        float alpha = alpha_of(t[b]);
        float ov = (1.0f - alpha) * (float)(1.0 / 21.0);
        float dv = alpha + ov;
        float Lo  = logf(ov + EPS);
        float dLd = logf(dv + EPS) - Lo;
        const float* xr = x + row * C_CLASSES;
        float sum = 0.0f;
        #pragma unroll
        for (int j = 0; j < C_CLASSES; ++j) sum += xr[j];
        float base = Lo * sum;
        float* o = out + row * C_CLASSES;
        #pragma unroll
        for (int j = 0; j < C_CLASSES; ++j)
            o[j] = fmaf(dLd, xr[j], base);
    }
}

__global__ void qt_generic_kernel(const int* __restrict__ t,
                                  float* __restrict__ out, long long n,
                                  long long per_batch) {
    long long stride = (long long)gridDim.x * blockDim.x;
    for (long long i = (long long)blockIdx.x * blockDim.x + threadIdx.x;
         i < n; i += stride) {
        int b = (int)(i / per_batch);
        float alpha = alpha_of(t[b]);
        float ov = (1.0f - alpha) * (float)(1.0 / 21.0);
        int p = (int)((i % per_batch) % CC);
        out[i] = (p % 22 == 0) ? (alpha + ov) : ov;
    }
}

extern "C" void kernel_launch(void* const* d_in, const int* in_sizes, int n_in,
                              void* d_out, int out_size) {
    const float* x = (const float*)d_in[0];
    const int*   t = (const int*)d_in[1];
    const int C = C_CLASSES;
    const int B = in_sizes[1];
    const int total = in_sizes[0];          // B*S*C
    const int S = total / (B * C);

    long long logits_elems = (long long)B * S * C;
    long long qt_elems     = (long long)B * S * C * C;
    bool want_qt = ((long long)out_size >= logits_elems + qt_elems);
    float* logits = (float*)d_out;
    float* qt     = logits + logits_elems;

    if (want_qt && (S % 256 == 0)) {
        const int ITERS = 32;
        int QX = S / (4 * ITERS);                // qt blocks per batch
        int LX = S / TILE_ROWS;                  // logits tiles per batch
        int n_qt = B * QX;
        int f4_per_batch = (S * CC) / 4;
        int stride_f4 = QX * CC;
        int grid = n_qt + B * LX;                // qt first, logits tail
        fused_kernel<ITERS><<<grid, CC>>>(x, t, logits, (float4*)qt,
                                          S, QX, LX, n_qt,
                                          f4_per_batch, stride_f4);
    } else {
        long long rows = (long long)B * S;
        int nb = (int)((rows + 255) / 256);
        if (nb > 4096) nb = 4096;
        logits_generic_kernel<<<nb, 256>>>(x, t, logits, rows, S);
        if (want_qt)
            qt_generic_kernel<<<4096, 256>>>(t, qt, qt_elems, (long long)S * CC);
    }
}

// round 9
// speedup vs baseline: 1.0208x; 1.0208x over previous
#include <cuda_runtime.h>
#include <math.h>

#define C_CLASSES 21
#define CC 441            // C*C
#define TILE_ROWS 256
#define TILE_ELEMS (TILE_ROWS * C_CLASSES)   // 5376
#define EPS 1e-10f

// ---------------------------------------------------------------------------
// alpha_cumprod collapses analytically: beta_i = 1 - ac[i+1]/ac[i] is clipped
// ONLY at i=199 (beta_199 ~ 1-5e-9 > 0.999; beta_198 ~ 0.994 < 0.999; beta>0
// always since cos^2 is decreasing on [0, pi/2]). ac[0] = 1.0f exactly in f32.
//   acum[t]   = ac[t+1]               for t <= 198
//   acum[199] = ac[199] * (1 - 0.999f)
// One cosf per block; verified rel_err ~1.4e-7 vs jnp reference.
// ---------------------------------------------------------------------------
__device__ __forceinline__ float alpha_of(int tb) {
    int idx = tb + 1;
    if (idx > 199) idx = 199;
    const float inv    = 1.0f / (1.0f + 1e-4f);
    const float halfpi = 1.57079632679489662f;
    float s = (float)idx * (1.0f / 200.0f);
    float c = cosf((s + 1e-4f) * inv * halfpi);
    float a = c * c;
    if (tb >= 199) a *= (1.0f - 0.999f);
    return a;
}

// ---------------------------------------------------------------------------
// Fused kernel, 1D grid, GLOBALLY ORDERED roles:
//   bid in [0, B*QX)            : q_t fill  (launches/executes FIRST)
//   bid in [B*QX, B*QX + B*LX)  : logits    (tail waves — minimal SM sharing)
//
// Round-6/7 finding: the qt store stream saturates the per-SM L1tex path;
// interleaved logits blocks steal it. Disjoint launch phases inside ONE
// kernel keep the serial behavior while removing the inter-launch gap.
//
// qt role: 441 threads, one per float4-residue of the CC=441 period. Each
// block writes ONE CONTIGUOUS span of ITERS*441 float4 (113 KB): iteration
// stride is 441 float4 = 1764 floats = 0 (mod 441), so each thread's float4
// payload stays loop-invariant: compute once, ITERS bare STG.128 with
// immediate offsets, sequential DRAM-page locality per SM.
//
// logits role: 256-row smem tile, fully coalesced load/store, conflict-free
// smem row sums (21 and 32 coprime). All 441 threads with bounds guards.
// ---------------------------------------------------------------------------
template <int ITERS>
__global__ __launch_bounds__(441) void fused_kernel(
    const float* __restrict__ x, const int* __restrict__ t,
    float* __restrict__ logits, float4* __restrict__ qt,
    int S, int QX, int LX, int n_qt_blocks, int f4_per_batch) {

    __shared__ float tile[TILE_ELEMS];
    __shared__ float rs[TILE_ROWS];

    const int bid = blockIdx.x;
    const int tid = threadIdx.x;

    if (bid < n_qt_blocks) {
        // ---- q_t fill (hot path: 462 MB of stores) ----
        const int b  = bid / QX;
        const int xq = bid - b * QX;

        const float alpha = alpha_of(__ldg(&t[b]));
        const float ov = (1.0f - alpha) * (float)(1.0 / 21.0);
        const float dv = alpha + ov;

        int p0 = 4 * tid;                    // (4*tid) mod 441
        if (p0 >= CC) p0 -= CC;
        if (p0 >= CC) p0 -= CC;
        if (p0 >= CC) p0 -= CC;
        float v[4];
        #pragma unroll
        for (int k = 0; k < 4; ++k) {
            int p = p0 + k;
            if (p >= CC) p -= CC;
            v[k] = (p % 22 == 0) ? dv : ov;  // diag positions: p = 22*c
        }
        const float4 val = make_float4(v[0], v[1], v[2], v[3]);

        // contiguous 441*ITERS-float4 span per block
        float4* o = qt + (size_t)b * f4_per_batch
                       + (size_t)xq * (CC * ITERS) + tid;
        #pragma unroll
        for (int it = 0; it < ITERS; ++it)
            o[it * CC] = val;
    } else {
        // ---- logits tile (tail waves) ----
        const int idx      = bid - n_qt_blocks;
        const int b        = idx / LX;
        const int tile_idx = idx - b * LX;

        const float alpha = alpha_of(__ldg(&t[b]));
        const float ov = (1.0f - alpha) * (float)(1.0 / 21.0);
        const float dv = alpha + ov;
        const float Lo  = logf(ov + EPS);
        const float dLd = logf(dv + EPS) - Lo;

        const size_t base = ((size_t)b * S + (size_t)tile_idx * TILE_ROWS)
                            * C_CLASSES;

        const float* xin = x + base;
        #pragma unroll
        for (int i = tid; i < TILE_ELEMS; i += 441)
            tile[i] = xin[i];
        __syncthreads();

        if (tid < TILE_ROWS) {
            float s = 0.0f;
            const int r0 = tid * C_CLASSES;
            #pragma unroll
            for (int j = 0; j < C_CLASSES; ++j) s += tile[r0 + j];
            rs[tid] = s;
        }
        __syncthreads();

        float* o = logits + base;
        #pragma unroll
        for (int i = tid; i < TILE_ELEMS; i += 441) {
            int row = (int)(((unsigned)i * 6242u) >> 17);  // i/21, i < 5376
            o[i] = fmaf(dLd, tile[i], Lo * rs[row]);
        }
    }
}

// ---------------------------------------------------------------------------
// Generic scalar fallbacks for unexpected shapes.
// ---------------------------------------------------------------------------
__global__ void logits_generic_kernel(const float* __restrict__ x,
                                      const int* __restrict__ t,
                                      float* __restrict__ out,
                                      long long rows, int S) {
    long long stride = (long long)gridDim.x * blockDim.x;
    for (long long row = (long long)blockIdx.x * blockDim.x + threadIdx.x;
         row < rows; row += stride) {
        int b = (int)(row / S);
        float alpha = alpha_of(t[b]);
        float ov = (1.0f - alpha) * (float)(1.0 / 21.0);
        float dv = alpha + ov;
        float Lo  = logf(ov + EPS);
        float dLd = logf(dv + EPS) - Lo;
        const float* xr = x + row * C_CLASSES;
        float sum = 0.0f;
        #pragma unroll
        for (int j = 0; j < C_CLASSES; ++j) sum += xr[j];
        float base = Lo * sum;
        float* o = out + row * C_CLASSES;
        #pragma unroll
        for (int j = 0; j < C_CLASSES; ++j)
            o[j] = fmaf(dLd, xr[j], base);
    }
}

__global__ void qt_generic_kernel(const int* __restrict__ t,
                                  float* __restrict__ out, long long n,
                                  long long per_batch) {
    long long stride = (long long)gridDim.x * blockDim.x;
    for (long long i = (long long)blockIdx.x * blockDim.x + threadIdx.x;
         i < n; i += stride) {
        int b = (int)(i / per_batch);
        float alpha = alpha_of(t[b]);
        float ov = (1.0f - alpha) * (float)(1.0 / 21.0);
        int p = (int)((i % per_batch) % CC);
        out[i] = (p % 22 == 0) ? (alpha + ov) : ov;
    }
}

extern "C" void kernel_launch(void* const* d_in, const int* in_sizes, int n_in,
                              void* d_out, int out_size) {
    const float* x = (const float*)d_in[0];
    const int*   t = (const int*)d_in[1];
    const int C = C_CLASSES;
    const int B = in_sizes[1];
    const int total = in_sizes[0];          // B*S*C
    const int S = total / (B * C);

    long long logits_elems = (long long)B * S * C;
    long long qt_elems     = (long long)B * S * C * C;
    bool want_qt = ((long long)out_size >= logits_elems + qt_elems);
    float* logits = (float*)d_out;
    float* qt     = logits + logits_elems;

    if (want_qt && (S % 256 == 0)) {
        const int ITERS = 16;
        int QX = S / (4 * ITERS);                // qt blocks per batch
        int LX = S / TILE_ROWS;                  // logits tiles per batch
        int n_qt = B * QX;
        int f4_per_batch = (S * CC) / 4;
        int grid = n_qt + B * LX;                // qt first, logits tail
        fused_kernel<ITERS><<<grid, CC>>>(x, t, logits, (float4*)qt,
                                          S, QX, LX, n_qt, f4_per_batch);
    } else {
        long long rows = (long long)B * S;
        int nb = (int)((rows + 255) / 256);
        if (nb > 4096) nb = 4096;
        logits_generic_kernel<<<nb, 256>>>(x, t, logits, rows, S);
        if (want_qt)
            qt_generic_kernel<<<4096, 256>>>(t, qt, qt_elems, (long long)S * CC);
    }
}

// round 10
// speedup vs baseline: 1.0347x; 1.0136x over previous
#include <cuda_runtime.h>
#include <math.h>

#define C_CLASSES 21
#define CC 441            // C*C
#define TILE_ROWS 256
#define TILE_ELEMS (TILE_ROWS * C_CLASSES)   // 5376 floats
#define TILE_F4    (TILE_ELEMS / 4)          // 1344 float4
#define EPS 1e-10f

// ---------------------------------------------------------------------------
// alpha_cumprod collapses analytically: beta_i = 1 - ac[i+1]/ac[i] is clipped
// ONLY at i=199 (beta_199 ~ 1-5e-9 > 0.999; beta_198 ~ 0.994 < 0.999; beta>0
// always since cos^2 is decreasing on [0, pi/2]). ac[0] = 1.0f exactly in f32.
//   acum[t]   = ac[t+1]               for t <= 198
//   acum[199] = ac[199] * (1 - 0.999f)
// One cosf per block; verified rel_err ~1.4e-7 vs jnp reference.
// ---------------------------------------------------------------------------
__device__ __forceinline__ float alpha_of(int tb) {
    int idx = tb + 1;
    if (idx > 199) idx = 199;
    const float inv    = 1.0f / (1.0f + 1e-4f);
    const float halfpi = 1.57079632679489662f;
    float s = (float)idx * (1.0f / 200.0f);
    float c = cosf((s + 1e-4f) * inv * halfpi);
    float a = c * c;
    if (tb >= 199) a *= (1.0f - 0.999f);
    return a;
}

// ---------------------------------------------------------------------------
// Fused kernel, 1D grid, GLOBALLY ORDERED roles:
//   bid in [0, B*QX)            : q_t fill  (launches/executes FIRST)
//   bid in [B*QX, B*QX + B*LX)  : logits    (tail waves — minimal SM sharing)
//
// Round-6/7 finding: the qt store stream saturates the per-SM L1tex path;
// interleaved logits blocks steal it. Disjoint launch phases inside ONE
// kernel keep the serial behavior while removing the inter-launch gap.
//
// qt role (round-7 proven config): 441 threads, one per float4-residue of
// the CC=441 period; iteration stride QX*CC float4 is a multiple of 441
// floats, so each thread's float4 payload is loop-invariant: compute once,
// ITERS bare STG.128.
//
// logits role: 256-row smem tile, float4-vectorized global load and store
// (tile byte offsets are multiples of 21504 -> 16B aligned), scalar
// conflict-free smem row sums (21 and 32 coprime).
// ---------------------------------------------------------------------------
template <int ITERS>
__global__ __launch_bounds__(441) void fused_kernel(
    const float* __restrict__ x, const int* __restrict__ t,
    float* __restrict__ logits, float4* __restrict__ qt,
    int S, int QX, int LX, int n_qt_blocks,
    int f4_per_batch, int stride_f4) {

    __shared__ float tile[TILE_ELEMS];
    __shared__ float rs[TILE_ROWS];

    const int bid = blockIdx.x;
    const int tid = threadIdx.x;

    if (bid < n_qt_blocks) {
        // ---- q_t fill (hot path: 462 MB of stores) ----
        const int b  = bid / QX;
        const int xq = bid - b * QX;

        const float alpha = alpha_of(__ldg(&t[b]));
        const float ov = (1.0f - alpha) * (float)(1.0 / 21.0);
        const float dv = alpha + ov;

        int p0 = 4 * tid;                    // (4*tid) mod 441
        if (p0 >= CC) p0 -= CC;
        if (p0 >= CC) p0 -= CC;
        if (p0 >= CC) p0 -= CC;
        float v[4];
        #pragma unroll
        for (int k = 0; k < 4; ++k) {
            int p = p0 + k;
            if (p >= CC) p -= CC;
            v[k] = (p % 22 == 0) ? dv : ov;  // diag positions: p = 22*c
        }
        const float4 val = make_float4(v[0], v[1], v[2], v[3]);

        float4* o = qt + (size_t)b * f4_per_batch
                       + (size_t)xq * CC + tid;
        #pragma unroll
        for (int it = 0; it < ITERS; ++it)
            o[(size_t)it * stride_f4] = val;
    } else {
        // ---- logits tile (tail waves), float4-vectorized ----
        const int idx      = bid - n_qt_blocks;
        const int b        = idx / LX;
        const int tile_idx = idx - b * LX;

        const float alpha = alpha_of(__ldg(&t[b]));
        const float ov = (1.0f - alpha) * (float)(1.0 / 21.0);
        const float dv = alpha + ov;
        const float Lo  = logf(ov + EPS);
        const float dLd = logf(dv + EPS) - Lo;

        const size_t base = ((size_t)b * S + (size_t)tile_idx * TILE_ROWS)
                            * C_CLASSES;

        const float4* xin4 = (const float4*)(x + base);
        float4* tile4 = (float4*)tile;
        #pragma unroll
        for (int i = tid; i < TILE_F4; i += 441)
            tile4[i] = xin4[i];
        __syncthreads();

        if (tid < TILE_ROWS) {
            float s = 0.0f;
            const int r0 = tid * C_CLASSES;
            #pragma unroll
            for (int j = 0; j < C_CLASSES; ++j) s += tile[r0 + j];
            rs[tid] = s;
        }
        __syncthreads();

        float4* o4 = (float4*)(logits + base);
        #pragma unroll
        for (int i = tid; i < TILE_F4; i += 441) {
            int e0 = i * 4;
            float4 v = tile4[i];
            float4 r;
            int row0 = (int)(((unsigned)(e0    ) * 6242u) >> 17);  // e/21, e<5376
            int row1 = (int)(((unsigned)(e0 + 1) * 6242u) >> 17);
            int row2 = (int)(((unsigned)(e0 + 2) * 6242u) >> 17);
            int row3 = (int)(((unsigned)(e0 + 3) * 6242u) >> 17);
            r.x = fmaf(dLd, v.x, Lo * rs[row0]);
            r.y = fmaf(dLd, v.y, Lo * rs[row1]);
            r.z = fmaf(dLd, v.z, Lo * rs[row2]);
            r.w = fmaf(dLd, v.w, Lo * rs[row3]);
            o4[i] = r;
        }
    }
}

// ---------------------------------------------------------------------------
// Generic scalar fallbacks for unexpected shapes.
// ---------------------------------------------------------------------------
__global__ void logits_generic_kernel(const float* __restrict__ x,
                                      const int* __restrict__ t,
                                      float* __restrict__ out,
                                      long long rows, int S) {
    long long stride = (long long)gridDim.x * blockDim.x;
    for (long long row = (long long)blockIdx.x * blockDim.x + threadIdx.x;
         row < rows; row += stride) {
        int b = (int)(row / S);
        float alpha = alpha_of(t[b]);
        float ov = (1.0f - alpha) * (float)(1.0 / 21.0);
        float dv = alpha + ov;
        float Lo  = logf(ov + EPS);
        float dLd = logf(dv + EPS) - Lo;
        const float* xr = x + row * C_CLASSES;
        float sum = 0.0f;
        #pragma unroll
        for (int j = 0; j < C_CLASSES; ++j) sum += xr[j];
        float base = Lo * sum;
        float* o = out + row * C_CLASSES;
        #pragma unroll
        for (int j = 0; j < C_CLASSES; ++j)
            o[j] = fmaf(dLd, xr[j], base);
    }
}

__global__ void qt_generic_kernel(const int* __restrict__ t,
                                  float* __restrict__ out, long long n,
                                  long long per_batch) {
    long long stride = (long long)gridDim.x * blockDim.x;
    for (long long i = (long long)blockIdx.x * blockDim.x + threadIdx.x;
         i < n; i += stride) {
        int b = (int)(i / per_batch);
        float alpha = alpha_of(t[b]);
        float ov = (1.0f - alpha) * (float)(1.0 / 21.0);
        int p = (int)((i % per_batch) % CC);
        out[i] = (p % 22 == 0) ? (alpha + ov) : ov;
    }
}

extern "C" void kernel_launch(void* const* d_in, const int* in_sizes, int n_in,
                              void* d_out, int out_size) {
    const float* x = (const float*)d_in[0];
    const int*   t = (const int*)d_in[1];
    const int C = C_CLASSES;
    const int B = in_sizes[1];
    const int total = in_sizes[0];          // B*S*C
    const int S = total / (B * C);

    long long logits_elems = (long long)B * S * C;
    long long qt_elems     = (long long)B * S * C * C;
    bool want_qt = ((long long)out_size >= logits_elems + qt_elems);
    float* logits = (float*)d_out;
    float* qt     = logits + logits_elems;

    if (want_qt && (S % 256 == 0)) {
        const int ITERS = 16;
        int QX = S / (4 * ITERS);                // qt blocks per batch
        int LX = S / TILE_ROWS;                  // logits tiles per batch
        int n_qt = B * QX;
        int f4_per_batch = (S * CC) / 4;
        int stride_f4 = QX * CC;
        int grid = n_qt + B * LX;                // qt first, logits tail
        fused_kernel<ITERS><<<grid, CC>>>(x, t, logits, (float4*)qt,
                                          S, QX, LX, n_qt,
                                          f4_per_batch, stride_f4);
    } else {
        long long rows = (long long)B * S;
        int nb = (int)((rows + 255) / 256);
        if (nb > 4096) nb = 4096;
        logits_generic_kernel<<<nb, 256>>>(x, t, logits, rows, S);
        if (want_qt)
            qt_generic_kernel<<<4096, 256>>>(t, qt, qt_elems, (long long)S * CC);
    }
}